// round 6
// baseline (speedup 1.0000x reference)
#include <cuda_runtime.h>
#include <cuda_fp16.h>
#include <cuda_bf16.h>

#define NMAX 100000
#define EMAX 1700000
#define D 64
#define RPB 64

// Scratch (allocation-free). INVARIANT at entry to kernel_launch:
// g_deg == 0, g_sums == 0, g_flag == 0, g_running == 0
// (zero-init at load; restored by fc_k / scanfin_k each call).
__device__ __half g_h[2 * NMAX * D];
__device__ float  g_y[2 * NMAX * D];
__device__ int    g_deg[2 * NMAX];
__device__ float  g_dinv[2 * NMAX];
__device__ int    g_rowptr[2 * (NMAX + 1)];
__device__ int    g_fill[2 * NMAX];
__device__ int    g_col[2 * EMAX];
__device__ float  g_sums[2 * D];
__device__ int    g_flag[2];
__device__ int    g_running[2];

// ---------------------------------------------------------------------------
// Fused: matmul layer-1 (blocks [0,mmb)) + degree histogram (blocks [mmb,..)).
__global__ void mmdeg_k(const float* __restrict__ x1, const float* __restrict__ x2,
                        const int* __restrict__ e1, const int* __restrict__ e2,
                        const float* __restrict__ W,
                        int n, int E1, int E2, int mmb, int degb) {
    int g = blockIdx.y;
    if (blockIdx.x < mmb) {
        // ---- matmul: h = x @ W (fp16 out), W[:,j] in regs, x via broadcast LDG
        int j = threadIdx.x & 63;
        int rg = threadIdx.x >> 6;
        const float* xin = g ? x2 : x1;
        __half* hout = g_h + (size_t)g * NMAX * D;

        float w[64];
#pragma unroll
        for (int k = 0; k < 64; k++) w[k] = W[k * 64 + j];

        int rend = min((blockIdx.x + 1) * RPB, n);
        for (int r = blockIdx.x * RPB + rg; r < rend; r += 4) {
            const float4* xv = reinterpret_cast<const float4*>(xin + (size_t)r * D);
            float a0 = 0.f, a1 = 0.f, a2 = 0.f, a3 = 0.f;
#pragma unroll
            for (int k4 = 0; k4 < 16; k4 += 4) {
                float4 t0 = xv[k4 + 0], t1 = xv[k4 + 1], t2 = xv[k4 + 2], t3 = xv[k4 + 3];
                a0 += t0.x * w[4*k4+0]  + t0.y * w[4*k4+1]  + t0.z * w[4*k4+2]  + t0.w * w[4*k4+3];
                a1 += t1.x * w[4*k4+4]  + t1.y * w[4*k4+5]  + t1.z * w[4*k4+6]  + t1.w * w[4*k4+7];
                a2 += t2.x * w[4*k4+8]  + t2.y * w[4*k4+9]  + t2.z * w[4*k4+10] + t2.w * w[4*k4+11];
                a3 += t3.x * w[4*k4+12] + t3.y * w[4*k4+13] + t3.z * w[4*k4+14] + t3.w * w[4*k4+15];
            }
            hout[(size_t)r * D + j] = __float2half_rn((a0 + a1) + (a2 + a3));
        }
    } else {
        // ---- degree: histogram of dst (int4 vectorized, grid-stride)
        int bx = blockIdx.x - mmb;
        int E = g ? E2 : E1;
        const int* dst = (g ? e2 : e1) + E;
        int* deg = g_deg + g * NMAX;
        int tot4 = E >> 2;
        int stride = degb * blockDim.x;
        for (int i = bx * blockDim.x + threadIdx.x; i < tot4; i += stride) {
            int4 d4 = reinterpret_cast<const int4*>(dst)[i];
            atomicAdd(&deg[d4.x], 1);
            atomicAdd(&deg[d4.y], 1);
            atomicAdd(&deg[d4.z], 1);
            atomicAdd(&deg[d4.w], 1);
        }
        for (int i = tot4 * 4 + bx * blockDim.x + threadIdx.x; i < E; i += stride)
            atomicAdd(&deg[dst[i]], 1);
    }
}

// ---------------------------------------------------------------------------
// Single-kernel chained exclusive scan of g_deg -> g_rowptr, plus
// fill-pointer init and dinv. 4096 elements per 1024-thread block.
// Chain state (g_flag/g_running) self-resets for the next replay.
__global__ void scanfin_k(int n, int E1, int E2, int nb) {
    __shared__ int s[1024];
    __shared__ int s_off;
    int g = blockIdx.y;
    int b = blockIdx.x;
    int base = b * 4096 + threadIdx.x * 4;
    const int* deg = g_deg + g * NMAX;

    int v[4];
    int sum = 0;
#pragma unroll
    for (int q = 0; q < 4; q++) {
        v[q] = (base + q < n) ? deg[base + q] : 0;
        sum += v[q];
    }
    s[threadIdx.x] = sum;
    __syncthreads();
#pragma unroll
    for (int off = 1; off < 1024; off <<= 1) {
        int t = 0;
        if (threadIdx.x >= off) t = s[threadIdx.x - off];
        __syncthreads();
        if (threadIdx.x >= off) s[threadIdx.x] += t;
        __syncthreads();
    }
    int excl = s[threadIdx.x] - sum;   // exclusive prefix within block
    int blocksum = s[1023];

    if (threadIdx.x == 0) {
        while (atomicAdd(&g_flag[g], 0) != b) { }          // wait for my turn
        int off = atomicAdd(&g_running[g], 0);
        if (b == nb - 1) atomicExch(&g_running[g], 0);      // reset for next call
        else             atomicExch(&g_running[g], off + blocksum);
        __threadfence();
        atomicExch(&g_flag[g], (b == nb - 1) ? 0 : b + 1);  // release / reset
        s_off = off;
    }
    __syncthreads();

    int gofs = s_off + excl;
#pragma unroll
    for (int q = 0; q < 4; q++) {
        int idx = base + q;
        if (idx < n) {
            g_rowptr[g * (NMAX + 1) + idx] = gofs;
            g_fill[g * NMAX + idx] = gofs;
            g_dinv[g * NMAX + idx] = rsqrtf((float)v[q] + 1.0f);
            gofs += v[q];
        }
    }
    if (b == 0 && threadIdx.x == 0) g_rowptr[g * (NMAX + 1) + n] = g ? E2 : E1;
}

// ---------------------------------------------------------------------------
__global__ void fill_k(const int* __restrict__ e1, const int* __restrict__ e2,
                       int E1, int E2, int fb) {
    int g = blockIdx.y;
    int E = g ? E2 : E1;
    const int* ei = g ? e2 : e1;
    const int* srcv = ei;
    const int* dstv = ei + E;
    int* fill = g_fill + g * NMAX;
    int* colg = g_col + (size_t)g * EMAX;
    int tot4 = E >> 2;
    int stride = fb * blockDim.x;
    for (int i = blockIdx.x * blockDim.x + threadIdx.x; i < tot4; i += stride) {
        int4 s4 = reinterpret_cast<const int4*>(srcv)[i];
        int4 d4 = reinterpret_cast<const int4*>(dstv)[i];
        colg[atomicAdd(&fill[d4.x], 1)] = s4.x;
        colg[atomicAdd(&fill[d4.y], 1)] = s4.y;
        colg[atomicAdd(&fill[d4.z], 1)] = s4.z;
        colg[atomicAdd(&fill[d4.w], 1)] = s4.w;
    }
    for (int i = tot4 * 4 + blockIdx.x * blockDim.x + threadIdx.x; i < E; i += stride)
        colg[atomicAdd(&fill[dstv[i]], 1)] = srcv[i];
}

// ---------------------------------------------------------------------------
// Warp-per-row aggregation, neighbor loop unrolled x8 for MLP.
// y[d] = relu(b + dinv[d]^2*h[d] + sum_nb dinv[s]*dinv[d]*h[s])
__global__ void aggregate_k(const float* __restrict__ b, int n, int do_pool) {
    int g = blockIdx.y;
    int lane = threadIdx.x & 31;
    int wid = threadIdx.x >> 5;
    int wpb = blockDim.x >> 5;
    int warp = blockIdx.x * wpb + wid;
    int nwarps = gridDim.x * wpb;

    const __half2* hv = reinterpret_cast<const __half2*>(g_h + (size_t)g * NMAX * D);
    float2* yv = reinterpret_cast<float2*>(g_y + (size_t)g * NMAX * D);
    const float* dinv = g_dinv + g * NMAX;
    const int* col = g_col + (size_t)g * EMAX;
    const int* rowptr = g_rowptr + g * (NMAX + 1);

    float2 bb = reinterpret_cast<const float2*>(b)[lane];
    float px = 0.f, py = 0.f;

    for (int row = warp; row < n; row += nwarps) {
        float dd = dinv[row];
        float2 hs = __half22float2(hv[row * 32 + lane]);
        float ns = dd * dd;
        float ax = hs.x * ns, ay = hs.y * ns;

        int p0 = rowptr[row];
        int p1 = rowptr[row + 1];
        int p = p0;
        for (; p + 8 <= p1; p += 8) {
            int i0 = __ldcs(&col[p + 0]), i1 = __ldcs(&col[p + 1]);
            int i2 = __ldcs(&col[p + 2]), i3 = __ldcs(&col[p + 3]);
            int i4 = __ldcs(&col[p + 4]), i5 = __ldcs(&col[p + 5]);
            int i6 = __ldcs(&col[p + 6]), i7 = __ldcs(&col[p + 7]);
            float n0 = dd * dinv[i0], n1 = dd * dinv[i1];
            float n2 = dd * dinv[i2], n3 = dd * dinv[i3];
            float n4 = dd * dinv[i4], n5 = dd * dinv[i5];
            float n6 = dd * dinv[i6], n7 = dd * dinv[i7];
            float2 v0 = __half22float2(hv[i0 * 32 + lane]);
            float2 v1 = __half22float2(hv[i1 * 32 + lane]);
            float2 v2 = __half22float2(hv[i2 * 32 + lane]);
            float2 v3 = __half22float2(hv[i3 * 32 + lane]);
            float2 v4 = __half22float2(hv[i4 * 32 + lane]);
            float2 v5 = __half22float2(hv[i5 * 32 + lane]);
            float2 v6 = __half22float2(hv[i6 * 32 + lane]);
            float2 v7 = __half22float2(hv[i7 * 32 + lane]);
            ax += v0.x * n0; ay += v0.y * n0;
            ax += v1.x * n1; ay += v1.y * n1;
            ax += v2.x * n2; ay += v2.y * n2;
            ax += v3.x * n3; ay += v3.y * n3;
            ax += v4.x * n4; ay += v4.y * n4;
            ax += v5.x * n5; ay += v5.y * n5;
            ax += v6.x * n6; ay += v6.y * n6;
            ax += v7.x * n7; ay += v7.y * n7;
        }
        for (; p + 4 <= p1; p += 4) {
            int i0 = __ldcs(&col[p + 0]), i1 = __ldcs(&col[p + 1]);
            int i2 = __ldcs(&col[p + 2]), i3 = __ldcs(&col[p + 3]);
            float n0 = dd * dinv[i0], n1 = dd * dinv[i1];
            float n2 = dd * dinv[i2], n3 = dd * dinv[i3];
            float2 v0 = __half22float2(hv[i0 * 32 + lane]);
            float2 v1 = __half22float2(hv[i1 * 32 + lane]);
            float2 v2 = __half22float2(hv[i2 * 32 + lane]);
            float2 v3 = __half22float2(hv[i3 * 32 + lane]);
            ax += v0.x * n0; ay += v0.y * n0;
            ax += v1.x * n1; ay += v1.y * n1;
            ax += v2.x * n2; ay += v2.y * n2;
            ax += v3.x * n3; ay += v3.y * n3;
        }
        for (; p < p1; p++) {
            int i0 = __ldcs(&col[p]);
            float n0 = dd * dinv[i0];
            float2 v0 = __half22float2(hv[i0 * 32 + lane]);
            ax += v0.x * n0; ay += v0.y * n0;
        }

        float yx = fmaxf(ax + bb.x, 0.f);
        float yy = fmaxf(ay + bb.y, 0.f);
        yv[row * 32 + lane] = make_float2(yx, yy);
        px += yx; py += yy;
    }

    if (do_pool) {
        __shared__ float s[64];
        if (threadIdx.x < 64) s[threadIdx.x] = 0.0f;
        __syncthreads();
        atomicAdd(&s[2 * lane + 0], px);
        atomicAdd(&s[2 * lane + 1], py);
        __syncthreads();
        if (threadIdx.x < 64) atomicAdd(&g_sums[g * 64 + threadIdx.x], s[threadIdx.x]);
    }
}

// ---------------------------------------------------------------------------
// Layer-2 matmul: h = y @ W (fp16 out)
__global__ void matmul2_k(const float* __restrict__ W, int n) {
    int g = blockIdx.y;
    int j = threadIdx.x & 63;
    int rg = threadIdx.x >> 6;
    const float* xin = g_y + (size_t)g * NMAX * D;
    __half* hout = g_h + (size_t)g * NMAX * D;

    float w[64];
#pragma unroll
    for (int k = 0; k < 64; k++) w[k] = W[k * 64 + j];

    int rend = min((blockIdx.x + 1) * RPB, n);
    for (int r = blockIdx.x * RPB + rg; r < rend; r += 4) {
        const float4* xv = reinterpret_cast<const float4*>(xin + (size_t)r * D);
        float a0 = 0.f, a1 = 0.f, a2 = 0.f, a3 = 0.f;
#pragma unroll
        for (int k4 = 0; k4 < 16; k4 += 4) {
            float4 t0 = xv[k4 + 0], t1 = xv[k4 + 1], t2 = xv[k4 + 2], t3 = xv[k4 + 3];
            a0 += t0.x * w[4*k4+0]  + t0.y * w[4*k4+1]  + t0.z * w[4*k4+2]  + t0.w * w[4*k4+3];
            a1 += t1.x * w[4*k4+4]  + t1.y * w[4*k4+5]  + t1.z * w[4*k4+6]  + t1.w * w[4*k4+7];
            a2 += t2.x * w[4*k4+8]  + t2.y * w[4*k4+9]  + t2.z * w[4*k4+10] + t2.w * w[4*k4+11];
            a3 += t3.x * w[4*k4+12] + t3.y * w[4*k4+13] + t3.z * w[4*k4+14] + t3.w * w[4*k4+15];
        }
        hout[(size_t)r * D + j] = __float2half_rn((a0 + a1) + (a2 + a3));
    }
}

// ---------------------------------------------------------------------------
// out[g][j] = fc_b[j] + sum_k mean[g][k] * fc_w[j,k]; restores zero-invariants.
__global__ void fc_k(const float* __restrict__ fcw, const float* __restrict__ fcb,
                     float* __restrict__ out, float invn, int n) {
    if (blockIdx.x == 0 && threadIdx.x < 128) {
        int g = threadIdx.x >> 6;
        int j = threadIdx.x & 63;
        float acc = fcb[j];
#pragma unroll 16
        for (int k = 0; k < D; k++)
            acc += (g_sums[g * 64 + k] * invn) * fcw[j * D + k];
        out[g * 64 + j] = acc;
    }
    __syncthreads();
    for (int i = blockIdx.x * blockDim.x + threadIdx.x; i < 2 * n;
         i += gridDim.x * blockDim.x)
        g_deg[i] = 0;
    if (blockIdx.x == 0 && threadIdx.x < 2 * D) g_sums[threadIdx.x] = 0.0f;
}

// ---------------------------------------------------------------------------
extern "C" void kernel_launch(void* const* d_in, const int* in_sizes, int n_in,
                              void* d_out, int out_size) {
    const float* x1  = (const float*)d_in[0];
    const float* x2  = (const float*)d_in[1];
    const int*   e1  = (const int*)d_in[2];
    const int*   e2  = (const int*)d_in[3];
    const float* W1  = (const float*)d_in[4];
    const float* b1  = (const float*)d_in[5];
    const float* W2  = (const float*)d_in[6];
    const float* b2  = (const float*)d_in[7];
    const float* fcw = (const float*)d_in[8];
    const float* fcb = (const float*)d_in[9];

    int n  = in_sizes[0] / D;
    int E1 = in_sizes[2] / 2;
    int E2 = in_sizes[3] / 2;
    float* out = (float*)d_out;

    const int T = 256;
    int mmb = (n + RPB - 1) / RPB;          // matmul blocks
    int degb = 1024;                        // degree blocks (grid-stride)
    int nb = (n + 4095) / 4096;             // scan blocks (<= 25)
    int fb = 2048;                          // fill blocks (grid-stride)

    mmdeg_k<<<dim3(mmb + degb, 2), T>>>(x1, x2, e1, e2, W1, n, E1, E2, mmb, degb); // 1
    scanfin_k<<<dim3(nb, 2), 1024>>>(n, E1, E2, nb);                               // 2
    fill_k<<<dim3(fb, 2), T>>>(e1, e2, E1, E2, fb);                                // 3
    aggregate_k<<<dim3(1184, 2), T>>>(b1, n, 0);                                   // 4 <- profiled
    matmul2_k<<<dim3(mmb, 2), T>>>(W2, n);                                         // 5
    aggregate_k<<<dim3(1184, 2), T>>>(b2, n, 1);                                   // 6
    fc_k<<<782, T>>>(fcw, fcb, out, 1.0f / (float)n, n);                           // 7
}

// round 7
// speedup vs baseline: 1.0459x; 1.0459x over previous
#include <cuda_runtime.h>
#include <cuda_fp16.h>
#include <cuda_bf16.h>

#define NMAX 100000
#define EMAX 1700000
#define D 64
#define RPB 64

// Scratch (allocation-free). INVARIANT at entry: g_deg == 0, g_sums == 0
// (zero-init at load; restored by fc_k each call).
__device__ __half g_h[2 * NMAX * D];    // h' = (x@W)*dinv  (fp16 gather source)
__device__ float  g_y[2 * NMAX * D];
__device__ int    g_deg[2 * NMAX];
__device__ float  g_dinv[2 * NMAX];
__device__ int    g_rowptr[2 * (NMAX + 1)];
__device__ int    g_fill[2 * NMAX];
__device__ int    g_col[2 * EMAX];
__device__ int    g_bsum[2 * 128];
__device__ float  g_sums[2 * D];

// ---------------------------------------------------------------------------
__global__ void degree_k(const int* __restrict__ e1, const int* __restrict__ e2,
                         int E1, int E2, int db) {
    int g = blockIdx.y;
    int E = g ? E2 : E1;
    const int* dst = (g ? e2 : e1) + E;
    int* deg = g_deg + g * NMAX;
    int stride = db * blockDim.x;
    if ((E & 3) == 0) {
        int tot4 = E >> 2;
        for (int i = blockIdx.x * blockDim.x + threadIdx.x; i < tot4; i += stride) {
            int4 d4 = reinterpret_cast<const int4*>(dst)[i];
            atomicAdd(&deg[d4.x], 1);
            atomicAdd(&deg[d4.y], 1);
            atomicAdd(&deg[d4.z], 1);
            atomicAdd(&deg[d4.w], 1);
        }
    } else {
        for (int i = blockIdx.x * blockDim.x + threadIdx.x; i < E; i += stride)
            atomicAdd(&deg[dst[i]], 1);
    }
}

// ---- exclusive scan of g_deg -> g_rowptr (block-local, 1024 elems/block) ---
__global__ void scan_block_k(int n) {
    __shared__ int s[1024];
    int g = blockIdx.y;
    int gid = blockIdx.x * 1024 + threadIdx.x;
    int v = (gid < n) ? g_deg[g * NMAX + gid] : 0;
    s[threadIdx.x] = v;
    __syncthreads();
#pragma unroll
    for (int off = 1; off < 1024; off <<= 1) {
        int t = 0;
        if (threadIdx.x >= off) t = s[threadIdx.x - off];
        __syncthreads();
        if (threadIdx.x >= off) s[threadIdx.x] += t;
        __syncthreads();
    }
    if (gid < n) g_rowptr[g * (NMAX + 1) + gid] = s[threadIdx.x] - v;  // exclusive
    if (threadIdx.x == 1023) g_bsum[g * 128 + blockIdx.x] = s[1023];
}

// rowptr += prefix(block sums); init fill ptr; dinv = rsqrt(deg+1)
__global__ void finalize_csr_k(int n, int E1, int E2, int nb) {
    int g = blockIdx.y;
    int gid = blockIdx.x * blockDim.x + threadIdx.x;
    int bucket = gid >> 10;
    int off = 0;
    const int* bs = g_bsum + g * 128;
    for (int i = 0; i < nb; i++)
        if (i < bucket) off += __ldg(&bs[i]);
    if (gid < n) {
        int rp = g_rowptr[g * (NMAX + 1) + gid] + off;
        g_rowptr[g * (NMAX + 1) + gid] = rp;
        g_fill[g * NMAX + gid] = rp;
        g_dinv[g * NMAX + gid] = rsqrtf((float)g_deg[g * NMAX + gid] + 1.0f);
    }
    if (gid == n) g_rowptr[g * (NMAX + 1) + n] = g ? E2 : E1;
}

// ---------------------------------------------------------------------------
// h' = (in @ W) * dinv  (fp16 out).  W[:,j] in regs; x row via broadcast LDG.
__global__ void matmul_k(const float* __restrict__ x1, const float* __restrict__ x2,
                         const float* __restrict__ W, int n) {
    int g = blockIdx.y;
    int j = threadIdx.x & 63;
    int rg = threadIdx.x >> 6;
    const float* xin = g ? x2 : x1;
    __half* hout = g_h + (size_t)g * NMAX * D;
    const float* dinv = g_dinv + g * NMAX;

    float w[64];
#pragma unroll
    for (int k = 0; k < 64; k++) w[k] = W[k * 64 + j];

    int rend = min((blockIdx.x + 1) * RPB, n);
    for (int r = blockIdx.x * RPB + rg; r < rend; r += 4) {
        const float4* xv = reinterpret_cast<const float4*>(xin + (size_t)r * D);
        float a0 = 0.f, a1 = 0.f, a2 = 0.f, a3 = 0.f;
#pragma unroll
        for (int k4 = 0; k4 < 16; k4 += 4) {
            float4 t0 = xv[k4 + 0], t1 = xv[k4 + 1], t2 = xv[k4 + 2], t3 = xv[k4 + 3];
            a0 += t0.x * w[4*k4+0]  + t0.y * w[4*k4+1]  + t0.z * w[4*k4+2]  + t0.w * w[4*k4+3];
            a1 += t1.x * w[4*k4+4]  + t1.y * w[4*k4+5]  + t1.z * w[4*k4+6]  + t1.w * w[4*k4+7];
            a2 += t2.x * w[4*k4+8]  + t2.y * w[4*k4+9]  + t2.z * w[4*k4+10] + t2.w * w[4*k4+11];
            a3 += t3.x * w[4*k4+12] + t3.y * w[4*k4+13] + t3.z * w[4*k4+14] + t3.w * w[4*k4+15];
        }
        hout[(size_t)r * D + j] = __float2half_rn(((a0 + a1) + (a2 + a3)) * dinv[r]);
    }
}

// Layer-2: h' = (y @ W) * dinv
__global__ void matmul2_k(const float* __restrict__ W, int n) {
    int g = blockIdx.y;
    int j = threadIdx.x & 63;
    int rg = threadIdx.x >> 6;
    const float* xin = g_y + (size_t)g * NMAX * D;
    __half* hout = g_h + (size_t)g * NMAX * D;
    const float* dinv = g_dinv + g * NMAX;

    float w[64];
#pragma unroll
    for (int k = 0; k < 64; k++) w[k] = W[k * 64 + j];

    int rend = min((blockIdx.x + 1) * RPB, n);
    for (int r = blockIdx.x * RPB + rg; r < rend; r += 4) {
        const float4* xv = reinterpret_cast<const float4*>(xin + (size_t)r * D);
        float a0 = 0.f, a1 = 0.f, a2 = 0.f, a3 = 0.f;
#pragma unroll
        for (int k4 = 0; k4 < 16; k4 += 4) {
            float4 t0 = xv[k4 + 0], t1 = xv[k4 + 1], t2 = xv[k4 + 2], t3 = xv[k4 + 3];
            a0 += t0.x * w[4*k4+0]  + t0.y * w[4*k4+1]  + t0.z * w[4*k4+2]  + t0.w * w[4*k4+3];
            a1 += t1.x * w[4*k4+4]  + t1.y * w[4*k4+5]  + t1.z * w[4*k4+6]  + t1.w * w[4*k4+7];
            a2 += t2.x * w[4*k4+8]  + t2.y * w[4*k4+9]  + t2.z * w[4*k4+10] + t2.w * w[4*k4+11];
            a3 += t3.x * w[4*k4+12] + t3.y * w[4*k4+13] + t3.z * w[4*k4+14] + t3.w * w[4*k4+15];
        }
        hout[(size_t)r * D + j] = __float2half_rn(((a0 + a1) + (a2 + a3)) * dinv[r]);
    }
}

// ---------------------------------------------------------------------------
__global__ void fill_k(const int* __restrict__ e1, const int* __restrict__ e2,
                       int E1, int E2, int fb) {
    int g = blockIdx.y;
    int E = g ? E2 : E1;
    const int* ei = g ? e2 : e1;
    const int* srcv = ei;
    const int* dstv = ei + E;
    int* fill = g_fill + g * NMAX;
    int* colg = g_col + (size_t)g * EMAX;
    int stride = fb * blockDim.x;
    if ((E & 3) == 0) {
        int tot4 = E >> 2;
        for (int i = blockIdx.x * blockDim.x + threadIdx.x; i < tot4; i += stride) {
            int4 s4 = reinterpret_cast<const int4*>(srcv)[i];
            int4 d4 = reinterpret_cast<const int4*>(dstv)[i];
            colg[atomicAdd(&fill[d4.x], 1)] = s4.x;
            colg[atomicAdd(&fill[d4.y], 1)] = s4.y;
            colg[atomicAdd(&fill[d4.z], 1)] = s4.z;
            colg[atomicAdd(&fill[d4.w], 1)] = s4.w;
        }
    } else {
        for (int i = blockIdx.x * blockDim.x + threadIdx.x; i < E; i += stride)
            colg[atomicAdd(&fill[dstv[i]], 1)] = srcv[i];
    }
}

// ---------------------------------------------------------------------------
// Warp-per-row aggregation with pre-normalized h':
//   y[d] = relu(b + dinv[d] * (h'[d] + sum_nb h'[s]))
// Inner loop per edge: gather half2 + HADD2 (fp16 accumulate, 2 alternating accs).
__global__ void aggregate_k(const float* __restrict__ b, int n, int do_pool) {
    int g = blockIdx.y;
    int lane = threadIdx.x & 31;
    int wid = threadIdx.x >> 5;
    int wpb = blockDim.x >> 5;
    int warp = blockIdx.x * wpb + wid;
    int nwarps = gridDim.x * wpb;

    const __half2* hv = reinterpret_cast<const __half2*>(g_h + (size_t)g * NMAX * D);
    float2* yv = reinterpret_cast<float2*>(g_y + (size_t)g * NMAX * D);
    const float* dinv = g_dinv + g * NMAX;
    const int* col = g_col + (size_t)g * EMAX;
    const int* rowptr = g_rowptr + g * (NMAX + 1);

    float2 bb = reinterpret_cast<const float2*>(b)[lane];
    float px = 0.f, py = 0.f;

    for (int row = warp; row < n; row += nwarps) {
        float dd = dinv[row];
        float2 hs = __half22float2(hv[row * 32 + lane]);   // self term h'[row]

        __half2 acc0 = __float2half2_rn(0.f);
        __half2 acc1 = __float2half2_rn(0.f);

        int p0 = rowptr[row];
        int p1 = rowptr[row + 1];
        int p = p0;
        // scalar head until 16B-aligned
        for (; p < p1 && (p & 3); p++)
            acc0 = __hadd2(acc0, hv[col[p] * 32 + lane]);
        // int4 main loop: 4 edges per iteration
        for (; p + 4 <= p1; p += 4) {
            int4 c4 = *reinterpret_cast<const int4*>(&col[p]);
            __half2 v0 = hv[c4.x * 32 + lane];
            __half2 v1 = hv[c4.y * 32 + lane];
            __half2 v2 = hv[c4.z * 32 + lane];
            __half2 v3 = hv[c4.w * 32 + lane];
            acc0 = __hadd2(acc0, v0);
            acc1 = __hadd2(acc1, v1);
            acc0 = __hadd2(acc0, v2);
            acc1 = __hadd2(acc1, v3);
        }
        for (; p < p1; p++)
            acc0 = __hadd2(acc0, hv[col[p] * 32 + lane]);

        float2 f0 = __half22float2(acc0);
        float2 f1 = __half22float2(acc1);
        float sx = hs.x + f0.x + f1.x;
        float sy = hs.y + f0.y + f1.y;
        float yx = fmaxf(fmaf(dd, sx, bb.x), 0.f);
        float yy = fmaxf(fmaf(dd, sy, bb.y), 0.f);
        yv[row * 32 + lane] = make_float2(yx, yy);
        px += yx; py += yy;
    }

    if (do_pool) {
        __shared__ float s[64];
        if (threadIdx.x < 64) s[threadIdx.x] = 0.0f;
        __syncthreads();
        atomicAdd(&s[2 * lane + 0], px);
        atomicAdd(&s[2 * lane + 1], py);
        __syncthreads();
        if (threadIdx.x < 64) atomicAdd(&g_sums[g * 64 + threadIdx.x], s[threadIdx.x]);
    }
}

// ---------------------------------------------------------------------------
// out[g][j] = fc_b[j] + sum_k mean[g][k] * fc_w[j,k]; restores zero-invariants.
__global__ void fc_k(const float* __restrict__ fcw, const float* __restrict__ fcb,
                     float* __restrict__ out, float invn, int n) {
    if (blockIdx.x == 0 && threadIdx.x < 128) {
        int g = threadIdx.x >> 6;
        int j = threadIdx.x & 63;
        float acc = fcb[j];
#pragma unroll 16
        for (int k = 0; k < D; k++)
            acc += (g_sums[g * 64 + k] * invn) * fcw[j * D + k];
        out[g * 64 + j] = acc;
    }
    __syncthreads();
    for (int i = blockIdx.x * blockDim.x + threadIdx.x; i < 2 * n;
         i += gridDim.x * blockDim.x)
        g_deg[i] = 0;
    if (blockIdx.x == 0 && threadIdx.x < 2 * D) g_sums[threadIdx.x] = 0.0f;
}

// ---------------------------------------------------------------------------
extern "C" void kernel_launch(void* const* d_in, const int* in_sizes, int n_in,
                              void* d_out, int out_size) {
    const float* x1  = (const float*)d_in[0];
    const float* x2  = (const float*)d_in[1];
    const int*   e1  = (const int*)d_in[2];
    const int*   e2  = (const int*)d_in[3];
    const float* W1  = (const float*)d_in[4];
    const float* b1  = (const float*)d_in[5];
    const float* W2  = (const float*)d_in[6];
    const float* b2  = (const float*)d_in[7];
    const float* fcw = (const float*)d_in[8];
    const float* fcb = (const float*)d_in[9];

    int n  = in_sizes[0] / D;
    int E1 = in_sizes[2] / 2;
    int E2 = in_sizes[3] / 2;
    float* out = (float*)d_out;

    const int T = 256;
    int mmb = (n + RPB - 1) / RPB;
    int nb = (n + 1023) / 1024;
    int db = 1024;   // degree blocks (grid-stride)
    int fb = 2048;   // fill blocks (grid-stride)

    degree_k<<<dim3(db, 2), T>>>(e1, e2, E1, E2, db);          // 1
    scan_block_k<<<dim3(nb, 2), 1024>>>(n);                    // 2
    finalize_csr_k<<<dim3((n + T) / T, 2), T>>>(n, E1, E2, nb);// 3
    matmul_k<<<dim3(mmb, 2), T>>>(x1, x2, W1, n);              // 4 <- profiled
    fill_k<<<dim3(fb, 2), T>>>(e1, e2, E1, E2, fb);            // 5
    aggregate_k<<<dim3(1184, 2), T>>>(b1, n, 0);               // 6
    matmul2_k<<<dim3(mmb, 2), T>>>(W2, n);                     // 7
    aggregate_k<<<dim3(1184, 2), T>>>(b2, n, 1);               // 8
    fc_k<<<782, T>>>(fcw, fcb, out, 1.0f / (float)n, n);       // 9
}

// round 10
// speedup vs baseline: 2.3459x; 2.2429x over previous
#include <cuda_runtime.h>
#include <cuda_fp16.h>
#include <cuda_bf16.h>

#define NMAX 100000
#define EMAX 1700000
#define D 64
#define MMROWS 128

// Scratch (allocation-free). INVARIANT at entry: g_deg == 0, g_sums == 0
// (zero-init at load; restored by fc_k each call).
__device__ __half g_h[2 * NMAX * D];    // h' = (x@W)*dinv  (fp16 gather source)
__device__ float  g_y[2 * NMAX * D];
__device__ int    g_deg[2 * NMAX];
__device__ float  g_dinv[2 * NMAX];
__device__ int    g_rowptr[2 * (NMAX + 1)];
__device__ int    g_fill[2 * NMAX];
__device__ int    g_col[2 * EMAX];
__device__ int    g_bsum[2 * 128];
__device__ float  g_sums[2 * D];

// ---------------------------------------------------------------------------
__global__ void degree_k(const int* __restrict__ e1, const int* __restrict__ e2,
                         int E1, int E2, int db) {
    int g = blockIdx.y;
    int E = g ? E2 : E1;
    const int* dst = (g ? e2 : e1) + E;
    int* deg = g_deg + g * NMAX;
    int stride = db * blockDim.x;
    if ((E & 3) == 0) {
        int tot4 = E >> 2;
        for (int i = blockIdx.x * blockDim.x + threadIdx.x; i < tot4; i += stride) {
            int4 d4 = reinterpret_cast<const int4*>(dst)[i];
            atomicAdd(&deg[d4.x], 1);
            atomicAdd(&deg[d4.y], 1);
            atomicAdd(&deg[d4.z], 1);
            atomicAdd(&deg[d4.w], 1);
        }
    } else {
        for (int i = blockIdx.x * blockDim.x + threadIdx.x; i < E; i += stride)
            atomicAdd(&deg[dst[i]], 1);
    }
}

// ---- exclusive scan of g_deg -> g_rowptr (block-local, 1024 elems/block) ---
__global__ void scan_block_k(int n) {
    __shared__ int s[1024];
    int g = blockIdx.y;
    int gid = blockIdx.x * 1024 + threadIdx.x;
    int v = (gid < n) ? g_deg[g * NMAX + gid] : 0;
    s[threadIdx.x] = v;
    __syncthreads();
#pragma unroll
    for (int off = 1; off < 1024; off <<= 1) {
        int t = 0;
        if (threadIdx.x >= off) t = s[threadIdx.x - off];
        __syncthreads();
        if (threadIdx.x >= off) s[threadIdx.x] += t;
        __syncthreads();
    }
    if (gid < n) g_rowptr[g * (NMAX + 1) + gid] = s[threadIdx.x] - v;  // exclusive
    if (threadIdx.x == 1023) g_bsum[g * 128 + blockIdx.x] = s[1023];
}

// rowptr += prefix(block sums); init fill ptr; dinv = rsqrt(deg+1)
__global__ void finalize_csr_k(int n, int E1, int E2, int nb) {
    int g = blockIdx.y;
    int gid = blockIdx.x * blockDim.x + threadIdx.x;
    int bucket = gid >> 10;
    int off = 0;
    const int* bs = g_bsum + g * 128;
    for (int i = 0; i < nb; i++)
        if (i < bucket) off += __ldg(&bs[i]);
    if (gid < n) {
        int rp = g_rowptr[g * (NMAX + 1) + gid] + off;
        g_rowptr[g * (NMAX + 1) + gid] = rp;
        g_fill[g * NMAX + gid] = rp;
        g_dinv[g * NMAX + gid] = rsqrtf((float)g_deg[g * NMAX + gid] + 1.0f);
    }
    if (gid == n) g_rowptr[g * (NMAX + 1) + n] = g ? E2 : E1;
}

// ---------------------------------------------------------------------------
// Tiled GEMM: h' = (in @ W) * dinv, fp16 out.
// Tile: 128 rows x 64 cols per 256-thread block. x staged TRANSPOSED in smem
// (xsT[k][row]) so k-step frag loads are contiguous float4s; W staged k-major.
// Thread (ty,tx) computes 8 rows x 4 cols with register blocking.
__global__ void matmul_k(const float* __restrict__ x1, const float* __restrict__ x2,
                         const float* __restrict__ W, int n, int from_y) {
    __shared__ float xsT[64][MMROWS];  // 32KB
    __shared__ float ws[64][64];       // 16KB  (total 48KB)

    int g = blockIdx.y;
    const float* xin = from_y ? (g_y + (size_t)g * NMAX * D) : (g ? x2 : x1);
    __half* hout = g_h + (size_t)g * NMAX * D;
    const float* dinv = g_dinv + g * NMAX;

    int tid = threadIdx.x;
    int row0 = blockIdx.x * MMROWS;

    // stage W (k-major = as stored): 1024 float4s, 4 per thread
    {
        const float4* Wv = reinterpret_cast<const float4*>(W);
        float4* wsv = reinterpret_cast<float4*>(&ws[0][0]);
#pragma unroll
        for (int i = 0; i < 4; i++)
            wsv[tid + 256 * i] = Wv[tid + 256 * i];
    }
    // stage x transposed: thread t handles half a row (row = t>>1, half = t&1)
    {
        int r = row0 + (tid >> 1);
        int half = tid & 1;
        int lrow = tid >> 1;
        if (r < n) {
            const float4* xv = reinterpret_cast<const float4*>(xin + (size_t)r * D);
#pragma unroll
            for (int k4 = 0; k4 < 8; k4++) {
                float4 v = xv[half * 8 + k4];
                int k = half * 32 + k4 * 4;
                xsT[k + 0][lrow] = v.x;
                xsT[k + 1][lrow] = v.y;
                xsT[k + 2][lrow] = v.z;
                xsT[k + 3][lrow] = v.w;
            }
        } else {
#pragma unroll
            for (int k4 = 0; k4 < 8; k4++) {
                int k = half * 32 + k4 * 4;
                xsT[k + 0][lrow] = 0.f;
                xsT[k + 1][lrow] = 0.f;
                xsT[k + 2][lrow] = 0.f;
                xsT[k + 3][lrow] = 0.f;
            }
        }
    }
    __syncthreads();

    int tx = tid & 15;   // col group: cols 4*tx .. 4*tx+3
    int ty = tid >> 4;   // row group: rows 8*ty .. 8*ty+7

    float acc[8][4];
#pragma unroll
    for (int i = 0; i < 8; i++)
#pragma unroll
        for (int j = 0; j < 4; j++) acc[i][j] = 0.f;

#pragma unroll 16
    for (int k = 0; k < 64; k++) {
        float4 a0 = *reinterpret_cast<const float4*>(&xsT[k][ty * 8]);
        float4 a1 = *reinterpret_cast<const float4*>(&xsT[k][ty * 8 + 4]);
        float4 b  = *reinterpret_cast<const float4*>(&ws[k][tx * 4]);
        float xf[8] = {a0.x, a0.y, a0.z, a0.w, a1.x, a1.y, a1.z, a1.w};
#pragma unroll
        for (int i = 0; i < 8; i++) {
            acc[i][0] += xf[i] * b.x;
            acc[i][1] += xf[i] * b.y;
            acc[i][2] += xf[i] * b.z;
            acc[i][3] += xf[i] * b.w;
        }
    }

    // store: 8 rows x 4 cols as fp16 (scaled by dinv[row]) -> one 8B store/row
#pragma unroll
    for (int i = 0; i < 8; i++) {
        int r = row0 + ty * 8 + i;
        if (r < n) {
            float dv = dinv[r];
            __half2 h0 = __floats2half2_rn(acc[i][0] * dv, acc[i][1] * dv);
            __half2 h1 = __floats2half2_rn(acc[i][2] * dv, acc[i][3] * dv);
            uint2 pk;
            pk.x = *reinterpret_cast<unsigned*>(&h0);
            pk.y = *reinterpret_cast<unsigned*>(&h1);
            *reinterpret_cast<uint2*>(&hout[(size_t)r * D + tx * 4]) = pk;
        }
    }
}

// ---------------------------------------------------------------------------
__global__ void fill_k(const int* __restrict__ e1, const int* __restrict__ e2,
                       int E1, int E2, int fb) {
    int g = blockIdx.y;
    int E = g ? E2 : E1;
    const int* ei = g ? e2 : e1;
    const int* srcv = ei;
    const int* dstv = ei + E;
    int* fill = g_fill + g * NMAX;
    int* colg = g_col + (size_t)g * EMAX;
    int stride = fb * blockDim.x;
    if ((E & 3) == 0) {
        int tot4 = E >> 2;
        for (int i = blockIdx.x * blockDim.x + threadIdx.x; i < tot4; i += stride) {
            int4 s4 = reinterpret_cast<const int4*>(srcv)[i];
            int4 d4 = reinterpret_cast<const int4*>(dstv)[i];
            colg[atomicAdd(&fill[d4.x], 1)] = s4.x;
            colg[atomicAdd(&fill[d4.y], 1)] = s4.y;
            colg[atomicAdd(&fill[d4.z], 1)] = s4.z;
            colg[atomicAdd(&fill[d4.w], 1)] = s4.w;
        }
    } else {
        for (int i = blockIdx.x * blockDim.x + threadIdx.x; i < E; i += stride)
            colg[atomicAdd(&fill[dstv[i]], 1)] = srcv[i];
    }
}

// ---------------------------------------------------------------------------
// Warp-per-row aggregation with pre-normalized h':
//   y[d] = relu(b + dinv[d] * (h'[d] + sum_nb h'[s]))
// Inner loop per edge: gather half2 + HADD2 (fp16 accumulate, 2 alternating accs).
__global__ void aggregate_k(const float* __restrict__ b, int n, int do_pool) {
    int g = blockIdx.y;
    int lane = threadIdx.x & 31;
    int wid = threadIdx.x >> 5;
    int wpb = blockDim.x >> 5;
    int warp = blockIdx.x * wpb + wid;
    int nwarps = gridDim.x * wpb;

    const __half2* hv = reinterpret_cast<const __half2*>(g_h + (size_t)g * NMAX * D);
    float2* yv = reinterpret_cast<float2*>(g_y + (size_t)g * NMAX * D);
    const float* dinv = g_dinv + g * NMAX;
    const int* col = g_col + (size_t)g * EMAX;
    const int* rowptr = g_rowptr + g * (NMAX + 1);

    float2 bb = reinterpret_cast<const float2*>(b)[lane];
    float px = 0.f, py = 0.f;

    for (int row = warp; row < n; row += nwarps) {
        float dd = dinv[row];
        float2 hs = __half22float2(hv[row * 32 + lane]);   // self term h'[row]

        __half2 acc0 = __float2half2_rn(0.f);
        __half2 acc1 = __float2half2_rn(0.f);

        int p0 = rowptr[row];
        int p1 = rowptr[row + 1];
        int p = p0;
        for (; p < p1 && (p & 3); p++)
            acc0 = __hadd2(acc0, hv[col[p] * 32 + lane]);
        for (; p + 4 <= p1; p += 4) {
            int4 c4 = *reinterpret_cast<const int4*>(&col[p]);
            __half2 v0 = hv[c4.x * 32 + lane];
            __half2 v1 = hv[c4.y * 32 + lane];
            __half2 v2 = hv[c4.z * 32 + lane];
            __half2 v3 = hv[c4.w * 32 + lane];
            acc0 = __hadd2(acc0, v0);
            acc1 = __hadd2(acc1, v1);
            acc0 = __hadd2(acc0, v2);
            acc1 = __hadd2(acc1, v3);
        }
        for (; p < p1; p++)
            acc0 = __hadd2(acc0, hv[col[p] * 32 + lane]);

        float2 f0 = __half22float2(acc0);
        float2 f1 = __half22float2(acc1);
        float sx = hs.x + f0.x + f1.x;
        float sy = hs.y + f0.y + f1.y;
        float yx = fmaxf(fmaf(dd, sx, bb.x), 0.f);
        float yy = fmaxf(fmaf(dd, sy, bb.y), 0.f);
        yv[row * 32 + lane] = make_float2(yx, yy);
        px += yx; py += yy;
    }

    if (do_pool) {
        __shared__ float s[64];
        if (threadIdx.x < 64) s[threadIdx.x] = 0.0f;
        __syncthreads();
        atomicAdd(&s[2 * lane + 0], px);
        atomicAdd(&s[2 * lane + 1], py);
        __syncthreads();
        if (threadIdx.x < 64) atomicAdd(&g_sums[g * 64 + threadIdx.x], s[threadIdx.x]);
    }
}

// ---------------------------------------------------------------------------
// out[g][j] = fc_b[j] + sum_k mean[g][k] * fc_w[j,k]; restores zero-invariants.
__global__ void fc_k(const float* __restrict__ fcw, const float* __restrict__ fcb,
                     float* __restrict__ out, float invn, int n) {
    if (blockIdx.x == 0 && threadIdx.x < 128) {
        int g = threadIdx.x >> 6;
        int j = threadIdx.x & 63;
        float acc = fcb[j];
#pragma unroll 16
        for (int k = 0; k < D; k++)
            acc += (g_sums[g * 64 + k] * invn) * fcw[j * D + k];
        out[g * 64 + j] = acc;
    }
    __syncthreads();
    for (int i = blockIdx.x * blockDim.x + threadIdx.x; i < 2 * n;
         i += gridDim.x * blockDim.x)
        g_deg[i] = 0;
    if (blockIdx.x == 0 && threadIdx.x < 2 * D) g_sums[threadIdx.x] = 0.0f;
}

// ---------------------------------------------------------------------------
extern "C" void kernel_launch(void* const* d_in, const int* in_sizes, int n_in,
                              void* d_out, int out_size) {
    const float* x1  = (const float*)d_in[0];
    const float* x2  = (const float*)d_in[1];
    const int*   e1  = (const int*)d_in[2];
    const int*   e2  = (const int*)d_in[3];
    const float* W1  = (const float*)d_in[4];
    const float* b1  = (const float*)d_in[5];
    const float* W2  = (const float*)d_in[6];
    const float* b2  = (const float*)d_in[7];
    const float* fcw = (const float*)d_in[8];
    const float* fcb = (const float*)d_in[9];

    int n  = in_sizes[0] / D;
    int E1 = in_sizes[2] / 2;
    int E2 = in_sizes[3] / 2;
    float* out = (float*)d_out;

    const int T = 256;
    int mmb = (n + MMROWS - 1) / MMROWS;
    int nb = (n + 1023) / 1024;
    int db = 1024;   // degree blocks (grid-stride)
    int fb = 2048;   // fill blocks (grid-stride)

    degree_k<<<dim3(db, 2), T>>>(e1, e2, E1, E2, db);          // 1
    scan_block_k<<<dim3(nb, 2), 1024>>>(n);                    // 2
    finalize_csr_k<<<dim3((n + T) / T, 2), T>>>(n, E1, E2, nb);// 3
    matmul_k<<<dim3(mmb, 2), T>>>(x1, x2, W1, n, 0);           // 4 <- profiled
    fill_k<<<dim3(fb, 2), T>>>(e1, e2, E1, E2, fb);            // 5
    aggregate_k<<<dim3(1184, 2), T>>>(b1, n, 0);               // 6
    matmul_k<<<dim3(mmb, 2), T>>>(x1, x2, W2, n, 1);           // 7
    aggregate_k<<<dim3(1184, 2), T>>>(b2, n, 1);               // 8
    fc_k<<<782, T>>>(fcw, fcb, out, 1.0f / (float)n, n);       // 9
}